// round 2
// baseline (speedup 1.0000x reference)
#include <cuda_runtime.h>

// FIR: out[b,t,c] = sum_{i=0..15} w[i,c] * x[b, t-15+i, c]   (causal, zero-padded)
// x: [B=64, T=2048, C=32] fp32, w: [F=16, C=32] fp32, out: [B, T, C] fp32.
//
// One thread = one channel x one 16-timestep group. Loads are front-batched
// (15 halo + 16 current independent LDGs -> MLP~31), then 256 FFMAs with
// fully static indices, then 16 STGs.

#define B_SZ 64
#define T_SZ 2048
#define C_SZ 32
#define F_SZ 16
#define GRP  16           // timesteps per thread (== F)
#define WARPS_PER_BLOCK 4

__global__ __launch_bounds__(C_SZ * WARPS_PER_BLOCK)
void fir_kernel(const float* __restrict__ x,
                const float* __restrict__ w,
                float* __restrict__ out) {
    const int c     = threadIdx.x;                            // lane = channel -> coalesced
    const int chunk = blockIdx.y * WARPS_PER_BLOCK + threadIdx.y;
    const int b     = blockIdx.x;
    const int t0    = chunk * GRP;

    const float* xb = x   + ((size_t)b * T_SZ + t0) * C_SZ + c;
    float*       ob = out + ((size_t)b * T_SZ + t0) * C_SZ + c;

    // Per-channel taps (L2-hot after the first wave).
    float wr[F_SZ];
#pragma unroll
    for (int i = 0; i < F_SZ; i++) wr[i] = w[i * C_SZ + c];

    // History: h[s] = x[t0 - 16 + s], s = 1..15 (h[0] never used).
    float h[F_SZ];
    h[0] = 0.0f;
    if (t0 != 0) {
#pragma unroll
        for (int s = 1; s < F_SZ; s++)
            h[s] = xb[(s - F_SZ) * C_SZ];
    } else {
#pragma unroll
        for (int s = 1; s < F_SZ; s++) h[s] = 0.0f;
    }

    // Current group: cur[k] = x[t0 + k], 16 independent loads (front-batched).
    float cur[GRP];
#pragma unroll
    for (int k = 0; k < GRP; k++)
        cur[k] = xb[k * C_SZ];

    // out[t0+u] = sum_{i=0..15} wr[i] * X(u - 15 + i),
    //   X(k) = (k < 0) ? h[16 + k] : cur[k]   -- all static after unroll.
    float res[GRP];
#pragma unroll
    for (int u = 0; u < GRP; u++) {
        float acc0 = 0.0f, acc1 = 0.0f;   // 2 chains: dep depth 16 -> 8
#pragma unroll
        for (int i = 0; i < F_SZ; i++) {
            const int k = u - (F_SZ - 1) + i;
            const float xv = (k < 0) ? h[F_SZ + k] : cur[k];
            if (i & 1) acc1 = fmaf(wr[i], xv, acc1);
            else       acc0 = fmaf(wr[i], xv, acc0);
        }
        res[u] = acc0 + acc1;
    }

#pragma unroll
    for (int u = 0; u < GRP; u++)
        ob[u * C_SZ] = res[u];
}

extern "C" void kernel_launch(void* const* d_in, const int* in_sizes, int n_in,
                              void* d_out, int out_size) {
    const float* x = (const float*)d_in[0];   // [64, 2048, 32]
    const float* w = (const float*)d_in[1];   // [16, 32]
    float* out = (float*)d_out;

    dim3 block(C_SZ, WARPS_PER_BLOCK);                        // 128 threads
    dim3 grid(B_SZ, (T_SZ / GRP) / WARPS_PER_BLOCK);          // (64, 32) = 2048 blocks
    fir_kernel<<<grid, block>>>(x, w, out);
}

// round 3
// speedup vs baseline: 1.0299x; 1.0299x over previous
#include <cuda_runtime.h>

// FIR: out[b,t,c] = sum_{i=0..15} w[i,c] * x[b, t-15+i, c]   (causal, zero-padded)
// x: [B=64, T=2048, C=32] fp32, w: [F=16, C=32] fp32, out: [B, T, C] fp32.
//
// Block = one (batch, 128-timestep tile). Tile + 15-halo staged in SMEM via
// coalesced LDG.128->STS.128 (layout identical to gmem), then each thread
// computes 16 outputs for one channel from 31 conflict-free LDS reads.

#define B_SZ 64
#define T_SZ 2048
#define C_SZ 32
#define F_SZ 16
#define TILE_T 128
#define GRP 16
#define THREADS 256                      // 8 warps: 128 t * 32 c / GRP outputs

#define HALO (F_SZ - 1)                  // 15
#define SMEM_T (TILE_T + HALO)           // 143
#define SMEM_FLOATS (SMEM_T * C_SZ)      // 4576
#define SMEM_VEC (SMEM_FLOATS / 4)       // 1144 float4
#define ZERO_VEC ((HALO * C_SZ) / 4)     // 120 leading zero-vectors when t0==0

__global__ __launch_bounds__(THREADS)
void fir_kernel(const float* __restrict__ x,
                const float* __restrict__ w,
                float* __restrict__ out) {
    __shared__ float4 tile[SMEM_VEC];

    const int tid = threadIdx.x;
    const int b   = blockIdx.x;
    const int t0  = blockIdx.y * TILE_T;

    // ---- cooperative staging: gmem [t0-15 .. t0+127] x [0..31] -> smem ----
    // gmem float offset of smem float 0:
    const long gbase = ((long)b * T_SZ + t0 - HALO) * C_SZ;   // multiple of 16 floats
    const float4* gx = (const float4*)(x + gbase);

    if (t0 != 0) {
#pragma unroll
        for (int k = 0; k < 5; k++) {
            const int v = tid + k * THREADS;
            if (v < SMEM_VEC) tile[v] = gx[v];
        }
    } else {
#pragma unroll
        for (int k = 0; k < 5; k++) {
            const int v = tid + k * THREADS;
            if (v < SMEM_VEC)
                tile[v] = (v < ZERO_VEC) ? make_float4(0.f, 0.f, 0.f, 0.f) : gx[v];
        }
    }

    // taps for this thread's channel (L2-hot)
    const int c = tid & (C_SZ - 1);
    float wr[F_SZ];
#pragma unroll
    for (int i = 0; i < F_SZ; i++) wr[i] = w[i * C_SZ + c];

    __syncthreads();

    // ---- compute: thread -> channel c, local outputs u0..u0+15 ----
    const int u0 = (tid >> 5) * GRP;     // 0,16,...,112
    const float* sm = (const float*)tile;

    // window: xw[j] = x[global t0 + u0 - 15 + j], j = 0..30  (31 LDS, bank=c)
    float xw[2 * F_SZ - 1];
#pragma unroll
    for (int j = 0; j < 2 * F_SZ - 1; j++)
        xw[j] = sm[(u0 + j) * C_SZ + c];

    float* ob = out + ((long)b * T_SZ + t0 + u0) * C_SZ + c;
#pragma unroll
    for (int u = 0; u < GRP; u++) {
        float acc0 = 0.0f, acc1 = 0.0f;          // 2 chains, dep depth 8
#pragma unroll
        for (int i = 0; i < F_SZ; i += 2) {
            acc0 = fmaf(wr[i],     xw[u + i],     acc0);
            acc1 = fmaf(wr[i + 1], xw[u + i + 1], acc1);
        }
        ob[u * C_SZ] = acc0 + acc1;
    }
}

extern "C" void kernel_launch(void* const* d_in, const int* in_sizes, int n_in,
                              void* d_out, int out_size) {
    const float* x = (const float*)d_in[0];   // [64, 2048, 32]
    const float* w = (const float*)d_in[1];   // [16, 32]
    float* out = (float*)d_out;

    dim3 grid(B_SZ, T_SZ / TILE_T);           // (64, 16) = 1024 blocks
    fir_kernel<<<grid, THREADS>>>(x, w, out);
}